// round 4
// baseline (speedup 1.0000x reference)
#include <cuda_runtime.h>

// GraphLoss: B=4, C=3, N=1024, G=2048, L=32
// out (float32): [closs, mloss, matches_gt(12x1025x1025)]
//
// Single-launch fully-fused pipeline:
//   blocks [0,192)   : per-(class,chunk) nearest-GT argmin + closs + sort keys
//   blocks [192,244) : zero-fill of d_out (output is 99.98% zeros)
//   blocks [244,256) : per-class bitonic chain + mloss + sparse scatter;
//                      last one finalizes scalars and resets sync counters.
// Cross-block ordering via global flag counters (release: fence+atomic after
// bar.sync; acquire: spin+fence+bar.sync). Chain blocks wait only on blocks
// that never wait -> no deadlock at any occupancy.

#define BC     12
#define NP     1024
#define GP     2048
#define NP1    1025
#define MAT    (NP1 * NP1)
#define THR    0.05590169943749474f
#define NCHUNK 16                    // pred chunks per class (64 preds each)
#define NSLICE 16                    // gt slices per block (128 gt each)
#define PREDS  64
#define NB     (BC * NCHUNK)         // 192 nearest blocks
#define ZB     52                    // zero-fill blocks
#define CB     BC                    // 12 chain blocks
#define GRID   (NB + ZB + CB)        // 256

typedef unsigned long long ull;

__device__ unsigned g_keys[BC * NP];
__device__ float    g_closs[BC * NCHUNK];
__device__ float    g_mloss[BC];
__device__ int      d_near_done[BC];   // -> NCHUNK each
__device__ int      d_zero_done;       // -> ZB
__device__ int      d_tick;            // -> CB

// ---- packed f32x2 helpers (Blackwell) -------------------------------------
__device__ __forceinline__ ull f2_add(ull a, ull b) {
    ull r; asm("add.rn.f32x2 %0,%1,%2;" : "=l"(r) : "l"(a), "l"(b)); return r;
}
__device__ __forceinline__ ull f2_mul(ull a, ull b) {
    ull r; asm("mul.rn.f32x2 %0,%1,%2;" : "=l"(r) : "l"(a), "l"(b)); return r;
}
__device__ __forceinline__ ull f2_fma(ull a, ull b, ull c) {
    ull r; asm("fma.rn.f32x2 %0,%1,%2,%3;" : "=l"(r) : "l"(a), "l"(b), "l"(c)); return r;
}
__device__ __forceinline__ ull f2_pack(float lo, float hi) {
    ull r;
    asm("mov.b64 %0,{%1,%2};" : "=l"(r)
        : "r"(__float_as_uint(lo)), "r"(__float_as_uint(hi)));
    return r;
}
__device__ __forceinline__ void f2_unpack(ull p, float& lo, float& hi) {
    unsigned a, b;
    asm("mov.b64 {%0,%1},%2;" : "=r"(a), "=r"(b) : "l"(p));
    lo = __uint_as_float(a); hi = __uint_as_float(b);
}

// ---- shared-memory union (roles never mix within a block) -----------------
struct SmNear {
    float gtx[GP];                 // 8 KB
    float gty[GP];                 // 8 KB
    ull   cand[NSLICE][PREDS];     // 8 KB
    float red[PREDS];
};
struct SmChain {
    unsigned sk[2][NP];            // 8 KB
    int      fwd[NP];              // 4 KB
    int      bwd[NP];              // 4 KB
    float    wr[32];
    int      last;
};
union SmAll { SmNear n; SmChain c; };

// ---------------------------------------------------------------------------
__global__ void __launch_bounds__(1024, 2) graph_loss_kernel(
    const float* __restrict__ matches,     // [BC,1025,1025] log-probs
    const float* __restrict__ positions,   // [BC,N,3]
    const float* __restrict__ gt_pts,      // [BC,G,2]
    const int*   __restrict__ gt_ins,      // [BC,G]
    const int*   __restrict__ gt_order,    // [BC,G]
    float*       __restrict__ dout,
    int out_size)
{
    __shared__ __align__(16) SmAll sm;
    const int bx  = blockIdx.x;
    const int tid = threadIdx.x;

    // ======================= nearest role ==================================
    if (bx < NB) {
        const int c     = bx >> 4;
        const int chunk = bx & 15;

        const float* gp = gt_pts + (size_t)c * GP * 2;
        for (int g = tid; g < GP; g += 1024) {
            sm.n.gtx[g] = (gp[2 * g + 0] + 30.0f) * (1.0f / 60.0f);
            sm.n.gty[g] = (gp[2 * g + 1] + 15.0f) * (1.0f / 30.0f);
        }
        __syncthreads();

        const int p = tid & 63;            // pred within chunk
        const int s = tid >> 6;            // gt slice 0..15
        const int i = chunk * PREDS + p;   // pred index in [0,N)

        const float* pp = positions + ((size_t)c * NP + i) * 3;
        const float px = pp[0], py = pp[1];
        const ull npx2 = f2_pack(-px, -px);
        const ull npy2 = f2_pack(-py, -py);

        const int g0 = s * 128;
        const float4* gx4 = (const float4*)(sm.n.gtx + g0);
        const float4* gy4 = (const float4*)(sm.n.gty + g0);

        float bd0 = 3.4e38f, bd1 = 3.4e38f;
        int   bi0 = 0,       bi1 = 0;

        #pragma unroll 4
        for (int it = 0; it < 32; it++) {
            const float4 gx = gx4[it];     // warp-uniform broadcast LDS
            const float4 gy = gy4[it];
            const ull gx01 = f2_pack(gx.x, gx.y), gx23 = f2_pack(gx.z, gx.w);
            const ull gy01 = f2_pack(gy.x, gy.y), gy23 = f2_pack(gy.z, gy.w);
            const ull dx01 = f2_add(gx01, npx2), dx23 = f2_add(gx23, npx2);
            const ull dy01 = f2_add(gy01, npy2), dy23 = f2_add(gy23, npy2);
            const ull d01  = f2_fma(dy01, dy01, f2_mul(dx01, dx01));
            const ull d23  = f2_fma(dy23, dy23, f2_mul(dx23, dx23));
            float d0, d1, d2, d3;
            f2_unpack(d01, d0, d1);
            f2_unpack(d23, d2, d3);
            const int g = g0 + it * 4;
            if (d0 < bd0) { bd0 = d0; bi0 = g;     }  // strict '<': first idx
            if (d1 < bd0) { bd0 = d1; bi0 = g + 1; }
            if (d2 < bd1) { bd1 = d2; bi1 = g + 2; }
            if (d3 < bd1) { bd1 = d3; bi1 = g + 3; }
        }

        const ull k0 = ((ull)__float_as_uint(bd0) << 32) | (unsigned)bi0;
        const ull k1 = ((ull)__float_as_uint(bd1) << 32) | (unsigned)bi1;
        sm.n.cand[s][p] = (k0 < k1) ? k0 : k1;
        __syncthreads();

        if (tid < PREDS) {
            ull k = sm.n.cand[0][tid];
            #pragma unroll
            for (int s2 = 1; s2 < NSLICE; s2++) {
                const ull kk = sm.n.cand[s2][tid];
                if (kk < k) k = kk;
            }
            const int   bi = (int)(k & 0xffffffffu);
            const float bd = __uint_as_float((unsigned)(k >> 32));
            const float nd = sqrtf(fmaxf(bd, 1e-12f));
            const int ins = gt_ins  [(size_t)c * GP + bi];
            const int ord = gt_order[(size_t)c * GP + bi];
            const int ik  = (nd < THR) ? ins : 64;
            const int gi  = chunk * PREDS + tid;
            g_keys[c * NP + gi] =
                ((unsigned)ik << 15) | (((unsigned)ord & 31u) << 10) | (unsigned)gi;
            // tid<64 => s==0, p==tid: px/py here ARE this pred's coords
            sm.n.red[tid] = fabsf(px - sm.n.gtx[bi]) + fabsf(py - sm.n.gty[bi]);
        }
        __syncthreads();
        if (tid < 32) {
            float v = sm.n.red[tid] + sm.n.red[tid + 32];
            #pragma unroll
            for (int o = 16; o > 0; o >>= 1)
                v += __shfl_down_sync(0xffffffffu, v, o);
            if (tid == 0) {
                g_closs[c * NCHUNK + chunk] = v;
                __threadfence();                 // release (after bar.sync above)
                atomicAdd(&d_near_done[c], 1);
            }
        }
        return;
    }

    // ======================= zero-fill role ================================
    if (bx < NB + ZB) {
        const int zb = bx - NB;
        const float4 z4 = make_float4(0.f, 0.f, 0.f, 0.f);
        float4* o4 = (float4*)dout;
        const int n4 = out_size >> 2;
        for (int idx = zb * 1024 + tid; idx < n4; idx += ZB * 1024)
            o4[idx] = z4;
        if (zb == 0 && tid < (out_size & 3))
            dout[(n4 << 2) + tid] = 0.f;
        __syncthreads();
        if (tid == 0) {
            __threadfence();
            atomicAdd(&d_zero_done, 1);
        }
        return;
    }

    // ======================= chain role ====================================
    const int c = bx - NB - ZB;

    if (tid == 0) {
        while (atomicAdd(&d_zero_done, 0) < ZB) { }
        while (atomicAdd(&d_near_done[c], 0) < NCHUNK) { }
        __threadfence();                          // acquire
    }
    __syncthreads();

    unsigned key = g_keys[c * NP + tid];
    sm.c.fwd[tid] = NP;
    sm.c.bwd[tid] = NP;

    // bitonic sort: shfl for j<32, double-buffered shared for j>=32
    int buf = 0;
    for (unsigned k = 2; k <= NP; k <<= 1) {
        const bool up = ((tid & k) == 0u);
        for (unsigned j = k >> 1; j > 0; j >>= 1) {
            unsigned other;
            if (j >= 32) {
                sm.c.sk[buf][tid] = key;
                __syncthreads();
                other = sm.c.sk[buf][tid ^ j];
                buf ^= 1;
            } else {
                other = __shfl_xor_sync(0xffffffffu, key, j);
            }
            const bool takeMin = (((tid & j) == 0u) == up);
            key = takeMin ? (key < other ? key : other)
                          : (key > other ? key : other);
        }
    }
    sm.c.sk[0][tid] = key;
    __syncthreads();

    // adjacent sorted entries in the same matched instance form a chain edge
    if (tid < NP - 1) {
        const unsigned a = sm.c.sk[0][tid], b = sm.c.sk[0][tid + 1];
        const unsigned ia = a >> 15, ib = b >> 15;
        if (ia == ib && ia < 64u) {
            sm.c.fwd[a & 1023u] = (int)(b & 1023u);
            sm.c.bwd[b & 1023u] = (int)(a & 1023u);
        }
    }
    __syncthreads();

    const int f = sm.c.fwd[tid];
    const int b = sm.c.bwd[tid];

    const float* lm = matches + (size_t)c * MAT;
    float v = lm[(size_t)tid * NP1 + f] + lm[(size_t)tid * NP1 + b];

    float* om = dout + 2 + (size_t)c * MAT;
    om[(size_t)tid * NP1 + f] = 1.0f;                  // mNN edge or to_bin
    if (b == NP) om[(size_t)NP * NP1 + tid] = 1.0f;    // from_bin row

    #pragma unroll
    for (int o = 16; o > 0; o >>= 1)
        v += __shfl_down_sync(0xffffffffu, v, o);
    if ((tid & 31) == 0) sm.c.wr[tid >> 5] = v;
    __syncthreads();
    if (tid < 32) {
        float w = sm.c.wr[tid];
        #pragma unroll
        for (int o = 16; o > 0; o >>= 1)
            w += __shfl_down_sync(0xffffffffu, w, o);
        if (tid == 0) g_mloss[c] = w;
    }
    __syncthreads();

    // ticket: last chain block finalizes scalars + resets counters for replay
    if (tid == 0) {
        __threadfence();
        const int t = atomicAdd(&d_tick, 1);
        sm.c.last = (t == CB - 1) ? 1 : 0;
        if (sm.c.last) __threadfence();               // acquire others' g_mloss
    }
    __syncthreads();

    if (sm.c.last) {
        if (tid < 32) {
            float cs = 0.0f, ms = 0.0f;
            for (int i2 = tid; i2 < BC * NCHUNK; i2 += 32) cs += g_closs[i2];
            if (tid < BC) ms = g_mloss[tid];
            #pragma unroll
            for (int o = 16; o > 0; o >>= 1) {
                cs += __shfl_down_sync(0xffffffffu, cs, o);
                ms += __shfl_down_sync(0xffffffffu, ms, o);
            }
            if (tid == 0) {
                dout[0] = cs / (float)(BC * NP * 2);
                dout[1] = -ms / (float)(BC * NP);
                d_tick = 0;                            // reset for next replay
                d_zero_done = 0;
            }
        }
        if (tid < BC) d_near_done[tid] = 0;
    }
}

// ---------------------------------------------------------------------------
extern "C" void kernel_launch(void* const* d_in, const int* in_sizes, int n_in,
                              void* d_out, int out_size)
{
    const float* matches   = (const float*)d_in[0];
    const float* positions = (const float*)d_in[1];
    // d_in[2] = masks (all ones, unused)
    const float* gt_pts    = (const float*)d_in[3];
    const int*   gt_ins    = (const int*)  d_in[4];
    const int*   gt_order  = (const int*)  d_in[5];

    graph_loss_kernel<<<GRID, 1024>>>(matches, positions, gt_pts, gt_ins,
                                      gt_order, (float*)d_out, out_size);
}

// round 5
// speedup vs baseline: 1.2715x; 1.2715x over previous
#include <cuda_runtime.h>

// GraphLoss: B=4, C=3, N=1024, G=2048, L=32
// out (float32): [closs, mloss, matches_gt(12x1025x1025)]
//
// Launch 1 (296 blocks x 512 thr, one wave, 64 regs):
//   [0,192)   nearest: 12 classes x 16 chunks of 64 preds; each thread owns
//             4 preds (register-tiled) and scans a 64-GT slice with packed
//             f32x2 math; exact first-index argmin via strict '<' + u64 keys.
//   [192,296) zero-fill of d_out (output is 99.98% zeros).
// Launch 2 (12 blocks x 1024 thr): per-class bitonic chain + mloss gather +
//   sparse scatter; last block (ticket) finalizes scalars, resets counter.

#define BC     12
#define NP     1024
#define GP     2048
#define NP1    1025
#define MAT    (NP1 * NP1)
#define THR    0.05590169943749474f
#define NCHUNK 16                 // chunks per class
#define CPRED  64                 // preds per chunk/block
#define NSL    32                 // gt slices per block
#define NB     (BC * NCHUNK)      // 192 nearest blocks
#define ZB     104                // zero blocks
#define GRID1  (NB + ZB)          // 296 = 148 SMs * 2

typedef unsigned long long ull;

__device__ unsigned g_keys[BC * NP];
__device__ float    g_closs[BC * NCHUNK];
__device__ float    g_mloss[BC];
__device__ int      d_tick;

// ---- packed f32x2 helpers (Blackwell) -------------------------------------
__device__ __forceinline__ ull f2_add(ull a, ull b) {
    ull r; asm("add.rn.f32x2 %0,%1,%2;" : "=l"(r) : "l"(a), "l"(b)); return r;
}
__device__ __forceinline__ ull f2_mul(ull a, ull b) {
    ull r; asm("mul.rn.f32x2 %0,%1,%2;" : "=l"(r) : "l"(a), "l"(b)); return r;
}
__device__ __forceinline__ ull f2_fma(ull a, ull b, ull c) {
    ull r; asm("fma.rn.f32x2 %0,%1,%2,%3;" : "=l"(r) : "l"(a), "l"(b), "l"(c)); return r;
}
__device__ __forceinline__ ull f2_pack(float lo, float hi) {
    ull r;
    asm("mov.b64 %0,{%1,%2};" : "=l"(r)
        : "r"(__float_as_uint(lo)), "r"(__float_as_uint(hi)));
    return r;
}
__device__ __forceinline__ void f2_unpack(ull p, float& lo, float& hi) {
    unsigned a, b;
    asm("mov.b64 {%0,%1},%2;" : "=r"(a), "=r"(b) : "l"(p));
    lo = __uint_as_float(a); hi = __uint_as_float(b);
}

// ---------------------------------------------------------------------------
// Launch 1: nearest (register-tiled) + zero-fill.
// ---------------------------------------------------------------------------
__global__ void __launch_bounds__(512, 2) nearest_zero_kernel(
    const float* __restrict__ positions,   // [BC,N,3]
    const float* __restrict__ gt_pts,      // [BC,G,2]
    const int*   __restrict__ gt_ins,      // [BC,G]
    const int*   __restrict__ gt_order,    // [BC,G]
    float*       __restrict__ dout,
    int out_size)
{
    const int bx  = blockIdx.x;
    const int tid = threadIdx.x;

    if (bx >= NB) {
        // ---- zero-fill role ----
        const int zb = bx - NB;
        const float4 z4 = make_float4(0.f, 0.f, 0.f, 0.f);
        float4* o4 = (float4*)dout;
        const int n4 = out_size >> 2;
        for (int idx = zb * 512 + tid; idx < n4; idx += ZB * 512)
            o4[idx] = z4;
        if (zb == 0 && tid < (out_size & 3))
            dout[(n4 << 2) + tid] = 0.f;
        return;
    }

    // ---- nearest role ----
    __shared__ __align__(16) float ngx[GP];        // negated normalized gt x
    __shared__ __align__(16) float ngy[GP];
    __shared__ ull   cand[NSL][CPRED / 4][4];      // 16 KB
    __shared__ float swr[2];

    const int c     = bx >> 4;                     // class
    const int chunk = bx & 15;                     // pred chunk (64 preds)

    const float* gp = gt_pts + (size_t)c * GP * 2;
    for (int g = tid; g < GP; g += 512) {
        ngx[g] = -((gp[2 * g + 0] + 30.0f) * (1.0f / 60.0f));
        ngy[g] = -((gp[2 * g + 1] + 15.0f) * (1.0f / 30.0f));
    }
    __syncthreads();

    const int quad  = tid & 15;                    // pred quad 0..15
    const int slice = tid >> 4;                    // gt slice 0..31 (64 gt)
    const int i0    = chunk * CPRED + quad * 4;    // first of 4 preds

    // load 4 pred coords, pre-duplicated as f32x2 constants
    ull Px[4], Py[4];
    #pragma unroll
    for (int p = 0; p < 4; p++) {
        const float* pp = positions + ((size_t)c * NP + i0 + p) * 3;
        const float px = pp[0], py = pp[1];
        Px[p] = f2_pack(px, px);
        Py[p] = f2_pack(py, py);
    }

    const int g0 = slice * 64;
    const ull* gx2 = (const ull*)(ngx + g0);       // (-x[g],-x[g+1]) pairs
    const ull* gy2 = (const ull*)(ngy + g0);

    float bd[4] = {3.4e38f, 3.4e38f, 3.4e38f, 3.4e38f};
    int   bi[4] = {0, 0, 0, 0};

    #pragma unroll 4
    for (int it = 0; it < 32; it++) {
        const ull gx = gx2[it];                    // warp: 2 uniform addrs
        const ull gy = gy2[it];
        const int g = g0 + it * 2;
        #pragma unroll
        for (int p = 0; p < 4; p++) {
            const ull dx = f2_add(Px[p], gx);      // px - x[g]
            const ull dy = f2_add(Py[p], gy);
            const ull d2 = f2_fma(dy, dy, f2_mul(dx, dx));
            float d0, d1;
            f2_unpack(d2, d0, d1);
            if (d0 < bd[p]) { bd[p] = d0; bi[p] = g;     }  // strict '<'
            if (d1 < bd[p]) { bd[p] = d1; bi[p] = g + 1; }
        }
    }

    #pragma unroll
    for (int p = 0; p < 4; p++)
        cand[slice][quad][p] =
            ((ull)__float_as_uint(bd[p]) << 32) | (unsigned)bi[p];
    __syncthreads();

    // epilogue: threads [0,64) reduce 32 slices per pred (u64 min = argmin
    // with first-index tiebreak), then closs + sort-key emission
    float v = 0.0f;
    if (tid < CPRED) {
        const int q = tid >> 2, p = tid & 3;
        ull k = cand[0][q][p];
        #pragma unroll
        for (int s = 1; s < NSL; s++) {
            const ull kk = cand[s][q][p];
            if (kk < k) k = kk;
        }
        const int   gb = (int)(k & 0xffffffffu);
        const float db = __uint_as_float((unsigned)(k >> 32));
        const float nd = sqrtf(fmaxf(db, 1e-12f));
        const int ins = gt_ins  [(size_t)c * GP + gb];
        const int ord = gt_order[(size_t)c * GP + gb];
        const int ik  = (nd < THR) ? ins : 64;
        const int gi  = chunk * CPRED + tid;
        g_keys[c * NP + gi] =
            ((unsigned)ik << 15) | (((unsigned)ord & 31u) << 10) | (unsigned)gi;

        const float* pp = positions + ((size_t)c * NP + gi) * 3;
        v = fabsf(pp[0] + ngx[gb]) + fabsf(pp[1] + ngy[gb]);
        #pragma unroll
        for (int o = 16; o > 0; o >>= 1)
            v += __shfl_down_sync(0xffffffffu, v, o);
        if ((tid & 31) == 0) swr[tid >> 5] = v;
    }
    __syncthreads();
    if (tid == 0) g_closs[c * NCHUNK + chunk] = swr[0] + swr[1];
}

// ---------------------------------------------------------------------------
// Launch 2: chain + mloss + sparse scatter + ticket finalize.
// ---------------------------------------------------------------------------
__global__ void __launch_bounds__(1024) chain_kernel(
    const float* __restrict__ matches,     // [BC,1025,1025]
    float*       __restrict__ dout)
{
    __shared__ unsigned sk[2][NP];
    __shared__ int   sfwd[NP];
    __shared__ int   sbwd[NP];
    __shared__ float wr[32];
    __shared__ int   slast;

    const int c   = blockIdx.x;
    const int tid = threadIdx.x;

    unsigned key = g_keys[c * NP + tid];
    sfwd[tid] = NP;
    sbwd[tid] = NP;

    // bitonic sort: shfl for j<32, double-buffered shared for j>=32
    int buf = 0;
    for (unsigned k = 2; k <= NP; k <<= 1) {
        const bool up = ((tid & k) == 0u);
        for (unsigned j = k >> 1; j > 0; j >>= 1) {
            unsigned other;
            if (j >= 32) {
                sk[buf][tid] = key;
                __syncthreads();
                other = sk[buf][tid ^ j];
                buf ^= 1;
            } else {
                other = __shfl_xor_sync(0xffffffffu, key, j);
            }
            const bool takeMin = (((tid & j) == 0u) == up);
            key = takeMin ? (key < other ? key : other)
                          : (key > other ? key : other);
        }
    }
    sk[0][tid] = key;
    __syncthreads();

    // adjacent sorted entries in the same matched instance form a chain edge
    if (tid < NP - 1) {
        const unsigned a = sk[0][tid], b = sk[0][tid + 1];
        const unsigned ia = a >> 15, ib = b >> 15;
        if (ia == ib && ia < 64u) {
            sfwd[a & 1023u] = (int)(b & 1023u);
            sbwd[b & 1023u] = (int)(a & 1023u);
        }
    }
    __syncthreads();

    const int f = sfwd[tid];
    const int b = sbwd[tid];

    const float* lm = matches + (size_t)c * MAT;
    float v = lm[(size_t)tid * NP1 + f] + lm[(size_t)tid * NP1 + b];

    float* om = dout + 2 + (size_t)c * MAT;
    om[(size_t)tid * NP1 + f] = 1.0f;                  // mNN edge or to_bin
    if (b == NP) om[(size_t)NP * NP1 + tid] = 1.0f;    // from_bin row

    #pragma unroll
    for (int o = 16; o > 0; o >>= 1)
        v += __shfl_down_sync(0xffffffffu, v, o);
    if ((tid & 31) == 0) wr[tid >> 5] = v;
    __syncthreads();
    if (tid < 32) {
        float w = wr[tid];
        #pragma unroll
        for (int o = 16; o > 0; o >>= 1)
            w += __shfl_down_sync(0xffffffffu, w, o);
        if (tid == 0) g_mloss[c] = w;
    }
    __syncthreads();

    // ticket: last block finalizes scalars and resets counter (graph-safe)
    if (tid == 0) {
        __threadfence();
        const int t = atomicAdd(&d_tick, 1);
        slast = (t == BC - 1) ? 1 : 0;
        if (slast) __threadfence();
    }
    __syncthreads();

    if (slast && tid < 32) {
        float cs = 0.0f, ms = 0.0f;
        for (int i2 = tid; i2 < BC * NCHUNK; i2 += 32) cs += g_closs[i2];
        if (tid < BC) ms = g_mloss[tid];
        #pragma unroll
        for (int o = 16; o > 0; o >>= 1) {
            cs += __shfl_down_sync(0xffffffffu, cs, o);
            ms += __shfl_down_sync(0xffffffffu, ms, o);
        }
        if (tid == 0) {
            dout[0] = cs / (float)(BC * NP * 2);
            dout[1] = -ms / (float)(BC * NP);
            d_tick = 0;                                // reset for next replay
        }
    }
}

// ---------------------------------------------------------------------------
extern "C" void kernel_launch(void* const* d_in, const int* in_sizes, int n_in,
                              void* d_out, int out_size)
{
    const float* matches   = (const float*)d_in[0];
    const float* positions = (const float*)d_in[1];
    // d_in[2] = masks (all ones, unused)
    const float* gt_pts    = (const float*)d_in[3];
    const int*   gt_ins    = (const int*)  d_in[4];
    const int*   gt_order  = (const int*)  d_in[5];
    float* out = (float*)d_out;

    nearest_zero_kernel<<<GRID1, 512>>>(positions, gt_pts, gt_ins, gt_order,
                                        out, out_size);
    chain_kernel<<<BC, 1024>>>(matches, out);
}